// round 3
// baseline (speedup 1.0000x reference)
#include <cuda_runtime.h>
#include <cstdint>
#include <math.h>

#define BATCH 64
#define SEQ   2048
#define INP   256
#define HID   512
#define NCTA  128
#define BGR   8      // batches per CTA
#define JGR   32     // hidden columns per CTA
#define PSTR  516    // padded row stride (floats): 516*4=2064B, rotates banks by 16B per row

// ---------------- scratch (no allocations allowed) ----------------
__device__ float    g_wx[(size_t)BATCH * SEQ * HID];   // 268 MB precomputed input projections
__device__ float    g_hbuf[2 * BATCH * HID];           // double-buffered hidden state
__device__ unsigned g_bar_cnt;
__device__ unsigned g_bar_gen;

// ---------------- packed fp32x2 FMA helpers (FFMA2) ----------------
__device__ __forceinline__ void fma2(unsigned long long &d, unsigned long long a, unsigned long long b) {
    asm("fma.rn.f32x2 %0, %1, %2, %0;" : "+l"(d) : "l"(a), "l"(b));
}
__device__ __forceinline__ unsigned long long pack2(float lo, float hi) {
    unsigned long long r;
    asm("mov.b64 %0, {%1, %2};" : "=l"(r) : "f"(lo), "f"(hi));
    return r;
}
__device__ __forceinline__ float lo2(unsigned long long v) { return __uint_as_float((unsigned)v); }
__device__ __forceinline__ float hi2(unsigned long long v) { return __uint_as_float((unsigned)(v >> 32)); }

// =====================================================================
// Phase 1: wx[b,s,:] = x[b,s,:] @ W + Wb      (M=131072, N=512, K=256)
// CTA tile 64x64, K-tiles of 64, thread tile 4x4, FFMA2 paired over n.
// =====================================================================
#define P1_BM 64
#define P1_BN 64
#define P1_BK 64

__global__ __launch_bounds__(256) void wx_kernel(const float* __restrict__ X,
                                                 const float* __restrict__ W,
                                                 const float* __restrict__ Wb) {
    __shared__ float Xs[P1_BM][P1_BK + 4];
    __shared__ float Ws[P1_BK][P1_BN + 4];

    const int t    = threadIdx.x;
    const int mpos = t >> 4;   // 0..15
    const int npos = t & 15;   // 0..15
    const int m0   = blockIdx.x * P1_BM;
    const int n0   = blockIdx.y * P1_BN;

    unsigned long long acc[4][2];
#pragma unroll
    for (int i = 0; i < 4; i++) { acc[i][0] = 0ull; acc[i][1] = 0ull; }

    for (int k0 = 0; k0 < INP; k0 += P1_BK) {
        // load X tile: 64 rows x 64 cols = 1024 float4
#pragma unroll
        for (int i = t; i < (P1_BM * P1_BK) / 4; i += 256) {
            int r = i >> 4;       // 16 float4 per row
            int c = i & 15;
            float4 v = *(const float4*)(X + (size_t)(m0 + r) * INP + k0 + c * 4);
            *(float4*)(&Xs[r][c * 4]) = v;
        }
        // load W tile: 64 rows x 64 cols
#pragma unroll
        for (int i = t; i < (P1_BK * P1_BN) / 4; i += 256) {
            int r = i >> 4;
            int c = i & 15;
            float4 v = *(const float4*)(W + (size_t)(k0 + r) * HID + n0 + c * 4);
            *(float4*)(&Ws[r][c * 4]) = v;
        }
        __syncthreads();

#pragma unroll
        for (int k = 0; k < P1_BK; k++) {
            ulonglong2 w = *(const ulonglong2*)(&Ws[k][npos * 4]);
#pragma unroll
            for (int i = 0; i < 4; i++) {
                float a = Xs[mpos * 4 + i][k];
                unsigned long long ad = pack2(a, a);
                fma2(acc[i][0], ad, w.x);
                fma2(acc[i][1], ad, w.y);
            }
        }
        __syncthreads();
    }

    float4 bb = *(const float4*)(Wb + n0 + npos * 4);
#pragma unroll
    for (int i = 0; i < 4; i++) {
        float4 v;
        v.x = lo2(acc[i][0]) + bb.x;
        v.y = hi2(acc[i][0]) + bb.y;
        v.z = lo2(acc[i][1]) + bb.z;
        v.w = hi2(acc[i][1]) + bb.w;
        *(float4*)(g_wx + (size_t)(m0 + mpos * 4 + i) * HID + n0 + npos * 4) = v;
    }
}

// =====================================================================
// Phase 2: persistent RNN scan. 128 CTAs (all resident), custom grid
// barrier per step. CTA = 8 batches x 32 hidden columns. U slice lives
// in SMEM for the whole kernel; h is re-staged from L2 each step.
// =====================================================================
__global__ __launch_bounds__(256, 1) void rnn_kernel(const float* __restrict__ Uw,
                                                     const float* __restrict__ Ub) {
    extern __shared__ float sm[];
    float* Ush = sm;                  // [JGR][PSTR]
    float* hsh = sm + JGR * PSTR;     // [BGR][PSTR]

    const int t   = threadIdx.x;
    const int cta = blockIdx.x;
    const int bg  = cta & 7;          // 8 batch groups
    const int jg  = cta >> 3;         // 16 column groups
    const int b0  = bg * BGR;
    const int j0  = jg * JGR;
    const int b   = t & 7;            // lane-fast over batch -> conflict-free LDS
    const int j   = t >> 3;           // 0..31

    // one-time: load U slice transposed -> Ush[j][k] = U[k][j0+j]
    for (int i = t; i < JGR * HID; i += 256) {
        int jj = i & 31;
        int k  = i >> 5;
        Ush[jj * PSTR + k] = Uw[(size_t)k * HID + j0 + jj];
    }
    const float ubj = Ub[j0 + j];
    const float* wxp = g_wx + (size_t)(b0 + b) * SEQ * HID + (j0 + j);
    float* const hrow_out_base = g_hbuf;
    __syncthreads();

    const float* hrow = hsh + b * PSTR;
    const float* urow = Ush + j * PSTR;

    for (int s = 0; s < SEQ; s++) {
        // issue wx load early; consumed ~1000+ cycles later
        float wxv = wxp[(size_t)s * HID];

        // stage h (this CTA's 8 batch rows) into SMEM
        if (s == 0) {
            for (int i = t; i < BGR * PSTR; i += 256) hsh[i] = 0.0f;
        } else {
            const float* hsrc = g_hbuf + (s & 1) * (BATCH * HID) + (size_t)b0 * HID;
            for (int i = t; i < (BGR * HID) / 4; i += 256) {
                int r  = i >> 7;    // 128 float4 per row
                int c4 = i & 127;
                float4 v = *(const float4*)(hsrc + (size_t)r * HID + c4 * 4);
                *(float4*)(&hsh[r * PSTR + c4 * 4]) = v;
            }
        }
        __syncthreads();

        // 512-length dot: h[b,:] . U[:,j], FFMA2 over k-pairs, 2 acc chains
        unsigned long long acc0 = 0ull, acc1 = 0ull;
#pragma unroll 8
        for (int k = 0; k < HID; k += 4) {
            ulonglong2 hv = *(const ulonglong2*)(hrow + k);
            ulonglong2 uv = *(const ulonglong2*)(urow + k);
            fma2(acc0, hv.x, uv.x);
            fma2(acc1, hv.y, uv.y);
        }
        float dot = (lo2(acc0) + hi2(acc0)) + (lo2(acc1) + hi2(acc1));
        float hnew = tanhf(wxv + ubj + dot);

        hrow_out_base[((s + 1) & 1) * (BATCH * HID) + (size_t)(b0 + b) * HID + (j0 + j)] = hnew;

        // ---- grid barrier ----
        __threadfence();
        __syncthreads();
        if (t == 0) {
            unsigned my = *(volatile unsigned*)&g_bar_gen;
            unsigned prev = atomicAdd(&g_bar_cnt, 1u);
            if (prev == NCTA - 1) {
                *(volatile unsigned*)&g_bar_cnt = 0u;
                __threadfence();
                atomicAdd(&g_bar_gen, 1u);
            } else {
                while (*(volatile unsigned*)&g_bar_gen == my) { }
            }
            __threadfence();
        }
        __syncthreads();
    }
}

// =====================================================================
// Phase 3: out = sigmoid(h_T @ V + Vb).  h_T lives in g_hbuf[0] (2048 even).
// =====================================================================
__global__ __launch_bounds__(128) void out_kernel(const float* __restrict__ Vw,
                                                  const float* __restrict__ Vb,
                                                  float* __restrict__ out) {
    const int bb = blockIdx.x;
    const int t  = threadIdx.x;
    const float* h = g_hbuf + (size_t)bb * HID;   // buffer 0

    float a0 = 0.f, a1 = 0.f;
    for (int k = t; k < HID; k += 128) {
        float hv = h[k];
        a0 += hv * Vw[k * 2 + 0];
        a1 += hv * Vw[k * 2 + 1];
    }
#pragma unroll
    for (int off = 16; off > 0; off >>= 1) {
        a0 += __shfl_down_sync(0xffffffffu, a0, off);
        a1 += __shfl_down_sync(0xffffffffu, a1, off);
    }
    __shared__ float p0[4], p1[4];
    if ((t & 31) == 0) { p0[t >> 5] = a0; p1[t >> 5] = a1; }
    __syncthreads();
    if (t == 0) {
        float s0 = p0[0] + p0[1] + p0[2] + p0[3] + Vb[0];
        float s1 = p1[0] + p1[1] + p1[2] + p1[3] + Vb[1];
        out[bb * 2 + 0] = 1.f / (1.f + expf(-s0));
        out[bb * 2 + 1] = 1.f / (1.f + expf(-s1));
    }
}

// =====================================================================
extern "C" void kernel_launch(void* const* d_in, const int* in_sizes, int n_in,
                              void* d_out, int out_size) {
    const float* x  = (const float*)d_in[0];
    const float* Ww = (const float*)d_in[1];
    const float* Wb = (const float*)d_in[2];
    const float* Uw = (const float*)d_in[3];
    const float* Ub = (const float*)d_in[4];
    const float* Vw = (const float*)d_in[5];
    const float* Vb = (const float*)d_in[6];
    float* out = (float*)d_out;

    // Phase 1: input projections for all timesteps
    dim3 g1((BATCH * SEQ) / P1_BM, HID / P1_BN);
    wx_kernel<<<g1, 256>>>(x, Ww, Wb);

    // Phase 2: persistent scan
    size_t smem2 = (size_t)(JGR + BGR) * PSTR * sizeof(float);   // ~82.6 KB
    cudaFuncSetAttribute(rnn_kernel, cudaFuncAttributeMaxDynamicSharedMemorySize, (int)smem2);
    rnn_kernel<<<NCTA, 256, smem2>>>(Uw, Ub);

    // Phase 3: readout
    out_kernel<<<BATCH, 128>>>(Vw, Vb, out);
}

// round 4
// speedup vs baseline: 1.3197x; 1.3197x over previous
#include <cuda_runtime.h>
#include <cstdint>
#include <math.h>

#define BATCH 64
#define SEQ   2048
#define INP   256
#define HID   512
#define NCTA  128
#define BGR   8      // batches per CTA
#define JGR   32     // hidden columns per CTA

// ---------------- scratch (no allocations allowed) ----------------
__device__ float    g_wx[(size_t)BATCH * SEQ * HID];   // 268 MB precomputed input projections
__device__ float    g_hbuf[2 * BATCH * HID];           // double-buffered hidden state
__device__ unsigned g_bar_cnt;
__device__ unsigned g_bar_gen;

// ---------------- packed fp32x2 FMA helpers (FFMA2) ----------------
__device__ __forceinline__ void fma2(unsigned long long &d, unsigned long long a, unsigned long long b) {
    asm("fma.rn.f32x2 %0, %1, %2, %0;" : "+l"(d) : "l"(a), "l"(b));
}
__device__ __forceinline__ unsigned long long pack2(float lo, float hi) {
    unsigned long long r;
    asm("mov.b64 %0, {%1, %2};" : "=l"(r) : "f"(lo), "f"(hi));
    return r;
}
__device__ __forceinline__ float lo2(unsigned long long v) { return __uint_as_float((unsigned)v); }
__device__ __forceinline__ float hi2(unsigned long long v) { return __uint_as_float((unsigned)(v >> 32)); }

// =====================================================================
// Phase 1: wx[b,s,:] = x[b,s,:] @ W + Wb      (M=131072, N=512, K=256)
// (unchanged from R1 — 822us, ~5% of total; revisit later)
// =====================================================================
#define P1_BM 64
#define P1_BN 64
#define P1_BK 64

__global__ __launch_bounds__(256) void wx_kernel(const float* __restrict__ X,
                                                 const float* __restrict__ W,
                                                 const float* __restrict__ Wb) {
    __shared__ float Xs[P1_BM][P1_BK + 4];
    __shared__ float Ws[P1_BK][P1_BN + 4];

    const int t    = threadIdx.x;
    const int mpos = t >> 4;   // 0..15
    const int npos = t & 15;   // 0..15
    const int m0   = blockIdx.x * P1_BM;
    const int n0   = blockIdx.y * P1_BN;

    unsigned long long acc[4][2];
#pragma unroll
    for (int i = 0; i < 4; i++) { acc[i][0] = 0ull; acc[i][1] = 0ull; }

    for (int k0 = 0; k0 < INP; k0 += P1_BK) {
#pragma unroll
        for (int i = t; i < (P1_BM * P1_BK) / 4; i += 256) {
            int r = i >> 4;
            int c = i & 15;
            float4 v = *(const float4*)(X + (size_t)(m0 + r) * INP + k0 + c * 4);
            *(float4*)(&Xs[r][c * 4]) = v;
        }
#pragma unroll
        for (int i = t; i < (P1_BK * P1_BN) / 4; i += 256) {
            int r = i >> 4;
            int c = i & 15;
            float4 v = *(const float4*)(W + (size_t)(k0 + r) * HID + n0 + c * 4);
            *(float4*)(&Ws[r][c * 4]) = v;
        }
        __syncthreads();

#pragma unroll
        for (int k = 0; k < P1_BK; k++) {
            ulonglong2 w = *(const ulonglong2*)(&Ws[k][npos * 4]);
#pragma unroll
            for (int i = 0; i < 4; i++) {
                float a = Xs[mpos * 4 + i][k];
                unsigned long long ad = pack2(a, a);
                fma2(acc[i][0], ad, w.x);
                fma2(acc[i][1], ad, w.y);
            }
        }
        __syncthreads();
    }

    float4 bb = *(const float4*)(Wb + n0 + npos * 4);
#pragma unroll
    for (int i = 0; i < 4; i++) {
        float4 v;
        v.x = lo2(acc[i][0]) + bb.x;
        v.y = hi2(acc[i][0]) + bb.y;
        v.z = lo2(acc[i][1]) + bb.z;
        v.w = hi2(acc[i][1]) + bb.w;
        *(float4*)(g_wx + (size_t)(m0 + mpos * 4 + i) * HID + n0 + npos * 4) = v;
    }
}

// =====================================================================
// Phase 2: persistent RNN scan, register-tiled.
// 128 CTAs, CTA = 8 batches x 32 hidden cols. 8 warps; each warp owns an
// 8b x 4j output tile with K split across 32 lanes (4 interleaved quads of
// 4 k each => warp-wide LDS.128 reads contiguous 512B, conflict-free).
// Per lane: 48 LDS.128 + 256 FFMA2 per step; 5-stage shuffle butterfly
// reduces lane partials so that lane L ends holding output index L.
// CTA smem traffic: 192KB/step (was 1MB in R1).
// =====================================================================
__global__ __launch_bounds__(256, 1) void rnn_kernel(const float* __restrict__ Uw,
                                                     const float* __restrict__ Ub) {
    extern __shared__ float sm[];
    float* Ush = sm;                  // [JGR][512]  (64 KB)  Ush[j][k] = U[k][j0+j]
    float* hsh = sm + JGR * HID;      // [BGR][512]  (16 KB)

    const int t    = threadIdx.x;
    const int cta  = blockIdx.x;
    const int bg   = cta & 7;
    const int jg   = cta >> 3;
    const int b0   = bg * BGR;
    const int j0   = jg * JGR;
    const int w    = t >> 5;
    const int lane = t & 31;

    // Final-output mapping after butterfly: lane L -> output o = L = (b<<2)|jl
    const int ob = lane >> 2;               // 0..7
    const int oj = (w << 2) | (lane & 3);   // 0..31 within CTA slice

    // one-time: load U slice transposed -> Ush[j][k] = U[k][j0+j]
    for (int i = t; i < JGR * HID; i += 256) {
        int jj = i & 31;
        int k  = i >> 5;
        Ush[jj * HID + k] = Uw[(size_t)k * HID + j0 + jj];
    }
    const float ubj = Ub[j0 + oj];
    const float* wxp = g_wx + (size_t)(b0 + ob) * SEQ * HID + (j0 + oj);
    __syncthreads();

    for (int s = 0; s < SEQ; s++) {
        // issue wx load early; consumed ~1500 cycles later
        float wxv = wxp[(size_t)s * HID];

        // stage this CTA's 8 h rows into SMEM (16KB, from L2)
        if (s == 0) {
            for (int i = t; i < BGR * HID; i += 256) hsh[i] = 0.0f;
        } else {
            const float* hsrc = g_hbuf + (s & 1) * (BATCH * HID) + (size_t)b0 * HID;
            for (int i = t; i < (BGR * HID) / 4; i += 256)
                ((float4*)hsh)[i] = ((const float4*)hsrc)[i];
        }
        __syncthreads();

        // 8b x 4j register tile, k split across lanes in 4 interleaved quads
        unsigned long long acc[32];
#pragma unroll
        for (int o = 0; o < 32; o++) acc[o] = 0ull;

#pragma unroll
        for (int qi = 0; qi < 4; qi++) {
            const int kb = qi * 128 + lane * 4;   // this lane's 4 contiguous k
            ulonglong2 hq[8], uq[4];
#pragma unroll
            for (int b = 0; b < 8; b++)
                hq[b] = *(const ulonglong2*)(hsh + b * HID + kb);
#pragma unroll
            for (int j = 0; j < 4; j++)
                uq[j] = *(const ulonglong2*)(Ush + (w * 4 + j) * HID + kb);
#pragma unroll
            for (int b = 0; b < 8; b++)
#pragma unroll
                for (int j = 0; j < 4; j++) {
                    fma2(acc[b * 4 + j], hq[b].x, uq[j].x);
                    fma2(acc[b * 4 + j], hq[b].y, uq[j].y);
                }
        }

        // fold k-parity, then butterfly-reduce across lanes (output o -> lane o)
        float v[32];
#pragma unroll
        for (int o = 0; o < 32; o++) v[o] = lo2(acc[o]) + hi2(acc[o]);

#define BFLY_STAGE(OFF, NKEEP)                                              \
        do {                                                                \
            const bool up = (lane & (OFF)) != 0;                            \
            _Pragma("unroll")                                               \
            for (int i = 0; i < (NKEEP); i++) {                             \
                float send = up ? v[i] : v[i + (NKEEP)];                    \
                float recv = __shfl_xor_sync(0xffffffffu, send, (OFF));     \
                v[i] = (up ? v[i + (NKEEP)] : v[i]) + recv;                 \
            }                                                               \
        } while (0)

        BFLY_STAGE(16, 16);
        BFLY_STAGE(8, 8);
        BFLY_STAGE(4, 4);
        BFLY_STAGE(2, 2);
        BFLY_STAGE(1, 1);
#undef BFLY_STAGE

        float hnew = tanhf(wxv + ubj + v[0]);
        g_hbuf[((s + 1) & 1) * (BATCH * HID) + (size_t)(b0 + ob) * HID + (j0 + oj)] = hnew;

        // ---- grid barrier ----
        __threadfence();
        __syncthreads();
        if (t == 0) {
            unsigned my = *(volatile unsigned*)&g_bar_gen;
            unsigned prev = atomicAdd(&g_bar_cnt, 1u);
            if (prev == NCTA - 1) {
                *(volatile unsigned*)&g_bar_cnt = 0u;
                __threadfence();
                atomicAdd(&g_bar_gen, 1u);
            } else {
                while (*(volatile unsigned*)&g_bar_gen == my) { }
            }
            __threadfence();
        }
        __syncthreads();
    }
}

// =====================================================================
// Phase 3: out = sigmoid(h_T @ V + Vb).  h_T lives in g_hbuf[0].
// =====================================================================
__global__ __launch_bounds__(128) void out_kernel(const float* __restrict__ Vw,
                                                  const float* __restrict__ Vb,
                                                  float* __restrict__ out) {
    const int bb = blockIdx.x;
    const int t  = threadIdx.x;
    const float* h = g_hbuf + (size_t)bb * HID;   // buffer 0

    float a0 = 0.f, a1 = 0.f;
    for (int k = t; k < HID; k += 128) {
        float hv = h[k];
        a0 += hv * Vw[k * 2 + 0];
        a1 += hv * Vw[k * 2 + 1];
    }
#pragma unroll
    for (int off = 16; off > 0; off >>= 1) {
        a0 += __shfl_down_sync(0xffffffffu, a0, off);
        a1 += __shfl_down_sync(0xffffffffu, a1, off);
    }
    __shared__ float p0[4], p1[4];
    if ((t & 31) == 0) { p0[t >> 5] = a0; p1[t >> 5] = a1; }
    __syncthreads();
    if (t == 0) {
        float s0 = p0[0] + p0[1] + p0[2] + p0[3] + Vb[0];
        float s1 = p1[0] + p1[1] + p1[2] + p1[3] + Vb[1];
        out[bb * 2 + 0] = 1.f / (1.f + expf(-s0));
        out[bb * 2 + 1] = 1.f / (1.f + expf(-s1));
    }
}

// =====================================================================
extern "C" void kernel_launch(void* const* d_in, const int* in_sizes, int n_in,
                              void* d_out, int out_size) {
    const float* x  = (const float*)d_in[0];
    const float* Ww = (const float*)d_in[1];
    const float* Wb = (const float*)d_in[2];
    const float* Uw = (const float*)d_in[3];
    const float* Ub = (const float*)d_in[4];
    const float* Vw = (const float*)d_in[5];
    const float* Vb = (const float*)d_in[6];
    float* out = (float*)d_out;

    // Phase 1: input projections for all timesteps
    dim3 g1((BATCH * SEQ) / P1_BM, HID / P1_BN);
    wx_kernel<<<g1, 256>>>(x, Ww, Wb);

    // Phase 2: persistent scan (80 KB dynamic smem)
    size_t smem2 = (size_t)(JGR + BGR) * HID * sizeof(float);
    cudaFuncSetAttribute(rnn_kernel, cudaFuncAttributeMaxDynamicSharedMemorySize, (int)smem2);
    rnn_kernel<<<NCTA, 256, smem2>>>(Uw, Ub);

    // Phase 3: readout
    out_kernel<<<BATCH, 128>>>(Vw, Vb, out);
}

// round 7
// speedup vs baseline: 1.6143x; 1.2232x over previous
#include <cuda_runtime.h>
#include <cstdint>
#include <math.h>

#define BATCH 64
#define SEQ   2048
#define INP   256
#define HID   512
#define NCTA  128
#define BGR   8      // batches per CTA
#define JGR   32     // hidden columns per CTA

// ---------------- scratch (no allocations allowed) ----------------
__device__ float    g_wx[(size_t)BATCH * SEQ * HID];   // 268 MB precomputed input projections
__device__ float    g_hbuf[2 * BATCH * HID];           // double-buffered hidden state
__device__ unsigned g_flags[NCTA];                     // per-CTA epoch flags (monotone across replays)

// ---------------- packed fp32x2 FMA helpers (FFMA2) ----------------
__device__ __forceinline__ void fma2(unsigned long long &d, unsigned long long a, unsigned long long b) {
    asm("fma.rn.f32x2 %0, %1, %2, %0;" : "+l"(d) : "l"(a), "l"(b));
}
__device__ __forceinline__ unsigned long long pack2(float lo, float hi) {
    unsigned long long r;
    asm("mov.b64 %0, {%1, %2};" : "=l"(r) : "f"(lo), "f"(hi));
    return r;
}
__device__ __forceinline__ float lo2(unsigned long long v) { return __uint_as_float((unsigned)v); }
__device__ __forceinline__ float hi2(unsigned long long v) { return __uint_as_float((unsigned)(v >> 32)); }

// ---------------- acquire/release flag ops ----------------
__device__ __forceinline__ unsigned ldacq(const unsigned* p) {
    unsigned v;
    asm volatile("ld.acquire.gpu.global.u32 %0, [%1];" : "=r"(v) : "l"(p) : "memory");
    return v;
}
__device__ __forceinline__ void strel(unsigned* p, unsigned v) {
    asm volatile("st.release.gpu.global.u32 [%0], %1;" :: "l"(p), "r"(v) : "memory");
}

// =====================================================================
// Phase 1: wx[b,s,:] = x[b,s,:] @ W + Wb      (M=131072, N=512, K=256)
// (~860us, ~8% of target total; revisit if it becomes the bottleneck)
// =====================================================================
#define P1_BM 64
#define P1_BN 64
#define P1_BK 64

__global__ __launch_bounds__(256) void wx_kernel(const float* __restrict__ X,
                                                 const float* __restrict__ W,
                                                 const float* __restrict__ Wb) {
    __shared__ float Xs[P1_BM][P1_BK + 4];
    __shared__ float Ws[P1_BK][P1_BN + 4];

    const int t    = threadIdx.x;
    const int mpos = t >> 4;   // 0..15
    const int npos = t & 15;   // 0..15
    const int m0   = blockIdx.x * P1_BM;
    const int n0   = blockIdx.y * P1_BN;

    unsigned long long acc[4][2];
#pragma unroll
    for (int i = 0; i < 4; i++) { acc[i][0] = 0ull; acc[i][1] = 0ull; }

    for (int k0 = 0; k0 < INP; k0 += P1_BK) {
#pragma unroll
        for (int i = t; i < (P1_BM * P1_BK) / 4; i += 256) {
            int r = i >> 4;
            int c = i & 15;
            float4 v = *(const float4*)(X + (size_t)(m0 + r) * INP + k0 + c * 4);
            *(float4*)(&Xs[r][c * 4]) = v;
        }
#pragma unroll
        for (int i = t; i < (P1_BK * P1_BN) / 4; i += 256) {
            int r = i >> 4;
            int c = i & 15;
            float4 v = *(const float4*)(W + (size_t)(k0 + r) * HID + n0 + c * 4);
            *(float4*)(&Ws[r][c * 4]) = v;
        }
        __syncthreads();

#pragma unroll
        for (int k = 0; k < P1_BK; k++) {
            ulonglong2 w = *(const ulonglong2*)(&Ws[k][npos * 4]);
#pragma unroll
            for (int i = 0; i < 4; i++) {
                float a = Xs[mpos * 4 + i][k];
                unsigned long long ad = pack2(a, a);
                fma2(acc[i][0], ad, w.x);
                fma2(acc[i][1], ad, w.y);
            }
        }
        __syncthreads();
    }

    float4 bb = *(const float4*)(Wb + n0 + npos * 4);
#pragma unroll
    for (int i = 0; i < 4; i++) {
        float4 v;
        v.x = lo2(acc[i][0]) + bb.x;
        v.y = hi2(acc[i][0]) + bb.y;
        v.z = lo2(acc[i][1]) + bb.z;
        v.w = hi2(acc[i][1]) + bb.w;
        *(float4*)(g_wx + (size_t)(m0 + mpos * 4 + i) * HID + n0 + npos * 4) = v;
    }
}

// =====================================================================
// Phase 2: persistent RNN scan, register-tiled, GROUP-LOCAL flag sync.
// 128 CTAs: CTA (bg,jg) = 8 batches x 32 hidden cols. The step-to-step
// dependency of CTA (bg,jg) is ONLY on the 16 CTAs sharing bg.
// Sync: producer stores h tile (weak STG) -> bar -> t0 st.release.gpu of
// flag[cta]=base+s+1. Consumers acquire-poll their group's 16 contiguous
// flags (one 64B line). base = own flag at entry (replay-safe epochs).
// Compute: 8 warps, each 8b x 4j output tile, K split over 32 lanes in 4
// interleaved quads (warp-wide LDS.128 = contiguous conflict-free 512B),
// then 5-stage shuffle butterfly (lane L ends with output index L).
// =====================================================================
__global__ __launch_bounds__(256, 1) void rnn_kernel(const float* __restrict__ Uw,
                                                     const float* __restrict__ Ub) {
    extern __shared__ float sm[];
    float* Ush = sm;                  // [JGR][512]  (64 KB)  Ush[j][k] = U[k][j0+j]
    float* hsh = sm + JGR * HID;      // [BGR][512]  (16 KB)

    const int t    = threadIdx.x;
    const int cta  = blockIdx.x;
    const int bg   = cta & 7;
    const int jg   = cta >> 3;
    const int b0   = bg * BGR;
    const int j0   = jg * JGR;
    const int w    = t >> 5;
    const int lane = t & 31;

    // Final-output mapping after butterfly: lane L -> output o = L = (b<<2)|jl
    const int ob = lane >> 2;               // 0..7
    const int oj = (w << 2) | (lane & 3);   // 0..31 within CTA slice

    // flags: group-contiguous layout flag[bg*16 + jg]
    const int fidx = bg * 16 + jg;
    unsigned* const fgrp = g_flags + bg * 16;
    const unsigned base = g_flags[fidx];    // consistent across CTAs after any full run

    // one-time: load U slice transposed -> Ush[j][k] = U[k][j0+j]
    for (int i = t; i < JGR * HID; i += 256) {
        int jj = i & 31;
        int k  = i >> 5;
        Ush[jj * HID + k] = Uw[(size_t)k * HID + j0 + jj];
    }
    const float ubj = Ub[j0 + oj];
    const float* wxp = g_wx + (size_t)(b0 + ob) * SEQ * HID + (j0 + oj);
    __syncthreads();

    for (int s = 0; s < SEQ; s++) {
        // issue wx load early; consumed ~2000+ cycles later
        float wxv = wxp[(size_t)s * HID];

        if (s == 0) {
            for (int i = t; i < BGR * HID; i += 256) hsh[i] = 0.0f;
        } else {
            // ---- group-local acquire poll (every warp; lanes 0..15) ----
            const unsigned tgt = base + (unsigned)s;
            unsigned v = tgt;
            if (lane < 16) v = ldacq(fgrp + lane);
            while (__any_sync(0xffffffffu, (int)(v - tgt) < 0)) {
                if (lane < 16 && (int)(v - tgt) < 0) v = ldacq(fgrp + lane);
            }
            // stage this CTA's 8 h rows (16KB) from L2 into SMEM
            const float* hsrc = g_hbuf + (s & 1) * (BATCH * HID) + (size_t)b0 * HID;
            for (int i = t; i < (BGR * HID) / 4; i += 256)
                ((float4*)hsh)[i] = ((const float4*)hsrc)[i];
        }
        __syncthreads();

        // 8b x 4j register tile, k split across lanes in 4 interleaved quads
        unsigned long long acc[32];
#pragma unroll
        for (int o = 0; o < 32; o++) acc[o] = 0ull;

#pragma unroll
        for (int qi = 0; qi < 4; qi++) {
            const int kb = qi * 128 + lane * 4;   // this lane's 4 contiguous k
            ulonglong2 hq[8], uq[4];
#pragma unroll
            for (int b = 0; b < 8; b++)
                hq[b] = *(const ulonglong2*)(hsh + b * HID + kb);
#pragma unroll
            for (int j = 0; j < 4; j++)
                uq[j] = *(const ulonglong2*)(Ush + (w * 4 + j) * HID + kb);
#pragma unroll
            for (int b = 0; b < 8; b++)
#pragma unroll
                for (int j = 0; j < 4; j++) {
                    fma2(acc[b * 4 + j], hq[b].x, uq[j].x);
                    fma2(acc[b * 4 + j], hq[b].y, uq[j].y);
                }
        }

        // fold k-parity, then butterfly-reduce across lanes (output o -> lane o)
        float v[32];
#pragma unroll
        for (int o = 0; o < 32; o++) v[o] = lo2(acc[o]) + hi2(acc[o]);

#define BFLY_STAGE(OFF, NKEEP)                                              \
        do {                                                                \
            const bool up = (lane & (OFF)) != 0;                            \
            _Pragma("unroll")                                               \
            for (int i = 0; i < (NKEEP); i++) {                             \
                float send = up ? v[i] : v[i + (NKEEP)];                    \
                float recv = __shfl_xor_sync(0xffffffffu, send, (OFF));     \
                v[i] = (up ? v[i + (NKEEP)] : v[i]) + recv;                 \
            }                                                               \
        } while (0)

        BFLY_STAGE(16, 16);
        BFLY_STAGE(8, 8);
        BFLY_STAGE(4, 4);
        BFLY_STAGE(2, 2);
        BFLY_STAGE(1, 1);
#undef BFLY_STAGE

        float hnew = tanhf(wxv + ubj + v[0]);
        g_hbuf[((s + 1) & 1) * (BATCH * HID) + (size_t)(b0 + ob) * HID + (j0 + oj)] = hnew;

        // bar orders all threads' h stores before t0's release; also protects
        // hsh against next iteration's staging overwrite.
        __syncthreads();
        if (t == 0) strel(g_flags + fidx, base + (unsigned)s + 1u);
    }
}

// =====================================================================
// Phase 3: out = sigmoid(h_T @ V + Vb).  h_T lives in g_hbuf[0].
// =====================================================================
__global__ __launch_bounds__(128) void out_kernel(const float* __restrict__ Vw,
                                                  const float* __restrict__ Vb,
                                                  float* __restrict__ out) {
    const int bb = blockIdx.x;
    const int t  = threadIdx.x;
    const float* h = g_hbuf + (size_t)bb * HID;   // buffer 0

    float a0 = 0.f, a1 = 0.f;
    for (int k = t; k < HID; k += 128) {
        float hv = h[k];
        a0 += hv * Vw[k * 2 + 0];
        a1 += hv * Vw[k * 2 + 1];
    }
#pragma unroll
    for (int off = 16; off > 0; off >>= 1) {
        a0 += __shfl_down_sync(0xffffffffu, a0, off);
        a1 += __shfl_down_sync(0xffffffffu, a1, off);
    }
    __shared__ float p0[4], p1[4];
    if ((t & 31) == 0) { p0[t >> 5] = a0; p1[t >> 5] = a1; }
    __syncthreads();
    if (t == 0) {
        float s0 = p0[0] + p0[1] + p0[2] + p0[3] + Vb[0];
        float s1 = p1[0] + p1[1] + p1[2] + p1[3] + Vb[1];
        out[bb * 2 + 0] = 1.f / (1.f + expf(-s0));
        out[bb * 2 + 1] = 1.f / (1.f + expf(-s1));
    }
}

// =====================================================================
extern "C" void kernel_launch(void* const* d_in, const int* in_sizes, int n_in,
                              void* d_out, int out_size) {
    const float* x  = (const float*)d_in[0];
    const float* Ww = (const float*)d_in[1];
    const float* Wb = (const float*)d_in[2];
    const float* Uw = (const float*)d_in[3];
    const float* Ub = (const float*)d_in[4];
    const float* Vw = (const float*)d_in[5];
    const float* Vb = (const float*)d_in[6];
    float* out = (float*)d_out;

    // Phase 1: input projections for all timesteps
    dim3 g1((BATCH * SEQ) / P1_BM, HID / P1_BN);
    wx_kernel<<<g1, 256>>>(x, Ww, Wb);

    // Phase 2: persistent scan (80 KB dynamic smem)
    size_t smem2 = (size_t)(JGR + BGR) * HID * sizeof(float);
    cudaFuncSetAttribute(rnn_kernel, cudaFuncAttributeMaxDynamicSharedMemorySize, (int)smem2);
    rnn_kernel<<<NCTA, 256, smem2>>>(Uw, Ub);

    // Phase 3: readout
    out_kernel<<<BATCH, 128>>>(Vw, Vb, out);
}